// round 15
// baseline (speedup 1.0000x reference)
#include <cuda_runtime.h>
#include <cuda_bf16.h>
#include <cuda_fp16.h>
#include <cstdint>

// Problem constants (match reference)
#define NN 100000
#define EE 1600000
#define NFEAT 256
#define NHID 64
#define NHEADS 4
#define HCAT 256   // NHEADS*NHID
#define NCLASS 32
#define ALPHA 0.2f

#define MPAD 128   // row padding so GEMMs need no bounds checks

// ---------------- scratch (device globals; no allocation at runtime) -------
__device__ __half g_Whi[NFEAT * HCAT];
__device__ __half g_W2hi[HCAT * NCLASS];
__device__ __half g_hcat[(size_t)(NN + MPAD) * HCAT];     // layer-1 features (fp16)
__device__ __half g_x1hi[(size_t)(NN + MPAD) * HCAT];
__device__ float g_ss[(NN + MPAD) * NHEADS];
__device__ float g_sd[(NN + MPAD) * NHEADS];
__device__ int   g_deg[NN];
__device__ int   g_rowptr[NN + 1];
__device__ int   g_cursor[NN];
__device__ int   g_col[EE];
__device__ int   g_blocksums[1024];
__device__ __half g_h2h[(size_t)(NN + MPAD) * NCLASS];    // layer-2 features (fp16)
__device__ float g_ss2[NN + MPAD];
__device__ float g_sd2[NN + MPAD];

__device__ __forceinline__ float eluf(float v) { return v > 0.f ? v : expm1f(v); }
__device__ __forceinline__ float lrelu(float v) { return v > 0.f ? v : ALPHA * v; }

// ---------------- prep: W_heads/W_out -> fp16, concat layout ---------------
__global__ void prep_kernel(const float* __restrict__ Wh, const float* __restrict__ W2) {
    int i = blockIdx.x * blockDim.x + threadIdx.x;
    if (i < NHEADS * NFEAT * NHID) {
        int h = i >> 14;
        int rem = i & 16383;
        int k = rem >> 6;
        int c = rem & 63;
        g_Whi[k * HCAT + (h << 6) + c] = __float2half_rn(Wh[i]);
    }
    if (i < HCAT * NCLASS) {
        g_W2hi[i] = __float2half_rn(W2[i]);
    }
}

// ---------------- monolithic CSR construction (persistent grid) -------------
#define CSR_BLOCKS 148
__device__ unsigned g_bar_cnt;
__device__ unsigned g_bar_gen;

__device__ __forceinline__ void gsync() {
    __syncthreads();
    if (threadIdx.x == 0) {
        unsigned my = atomicAdd(&g_bar_gen, 0u);
        __threadfence();
        if (atomicAdd(&g_bar_cnt, 1u) + 1u == (unsigned)CSR_BLOCKS) {
            atomicExch(&g_bar_cnt, 0u);
            __threadfence();
            atomicAdd(&g_bar_gen, 1u);
        } else {
            while (atomicAdd(&g_bar_gen, 0u) == my) { }
        }
        __threadfence();
    }
    __syncthreads();
}

__global__ __launch_bounds__(1024, 1) void csr_mono(const int* __restrict__ src,
                                                    const int* __restrict__ dst,
                                                    int n, int e) {
    int tid = blockIdx.x * 1024 + threadIdx.x;
    const int nthr = CSR_BLOCKS * 1024;
    __shared__ int s[1024];
    int t = threadIdx.x;

    // phase 0: zero deg
    for (int i = tid; i < n; i += nthr) g_deg[i] = 0;
    gsync();

    // phase 1: histogram
    for (int i = tid; i < e; i += nthr) atomicAdd(&g_deg[src[i]], 1);
    gsync();

    // phase 2a: block-local exclusive scan over 1024-node chunks
    int nb = (n + 1023) >> 10;   // 98 chunks
    int idx = blockIdx.x * 1024 + t;
    if ((int)blockIdx.x < nb) {
        int v = (idx < n) ? g_deg[idx] : 0;
        s[t] = v;
        __syncthreads();
#pragma unroll
        for (int off = 1; off < 1024; off <<= 1) {
            int xv = (t >= off) ? s[t - off] : 0;
            __syncthreads();
            s[t] += xv;
            __syncthreads();
        }
        if (idx < n) g_rowptr[idx] = s[t] - v;     // local exclusive
        if (t == 1023) g_blocksums[blockIdx.x] = s[1023];
    }
    gsync();

    // phase 2b: block 0 scans chunk sums (exclusive)
    if (blockIdx.x == 0) {
        int v = (t < nb) ? g_blocksums[t] : 0;
        s[t] = v;
        __syncthreads();
#pragma unroll
        for (int off = 1; off < 1024; off <<= 1) {
            int xv = (t >= off) ? s[t - off] : 0;
            __syncthreads();
            s[t] += xv;
            __syncthreads();
        }
        if (t < nb) g_blocksums[t] = s[t] - v;
    }
    gsync();

    // phase 2c: add chunk offsets -> rowptr, cursor
    for (int i = tid; i < n; i += nthr) {
        int r = g_rowptr[i] + g_blocksums[i >> 10];
        g_rowptr[i] = r;
        g_cursor[i] = r;
    }
    if (tid == 0) g_rowptr[n] = e;
    gsync();

    // phase 3: scatter
    for (int i = tid; i < e; i += nthr) {
        int sN = src[i];
        int p = atomicAdd(&g_cursor[sN], 1);
        g_col[p] = dst[i];
    }
}

// ---------------- mma helpers -----------------------------------------------
__device__ __forceinline__ void ldsm4(uint32_t& r0, uint32_t& r1, uint32_t& r2, uint32_t& r3, uint32_t addr) {
    asm volatile("ldmatrix.sync.aligned.m8n8.x4.shared.b16 {%0,%1,%2,%3}, [%4];"
                 : "=r"(r0), "=r"(r1), "=r"(r2), "=r"(r3) : "r"(addr));
}
__device__ __forceinline__ void ldsm4t(uint32_t& r0, uint32_t& r1, uint32_t& r2, uint32_t& r3, uint32_t addr) {
    asm volatile("ldmatrix.sync.aligned.m8n8.x4.trans.shared.b16 {%0,%1,%2,%3}, [%4];"
                 : "=r"(r0), "=r"(r1), "=r"(r2), "=r"(r3) : "r"(addr));
}
__device__ __forceinline__ void mma16816(float* c, const uint32_t* a, uint32_t b0, uint32_t b1) {
    asm volatile("mma.sync.aligned.m16n8k16.row.col.f32.f16.f16.f32 "
                 "{%0,%1,%2,%3}, {%4,%5,%6,%7}, {%8,%9}, {%0,%1,%2,%3};"
                 : "+f"(c[0]), "+f"(c[1]), "+f"(c[2]), "+f"(c[3])
                 : "r"(a[0]), "r"(a[1]), "r"(a[2]), "r"(a[3]), "r"(b0), "r"(b1));
}
__device__ __forceinline__ void cpa16(uint32_t s, const void* g) {
    asm volatile("cp.async.cg.shared.global [%0], [%1], 16;" :: "r"(s), "l"(g));
}

// ---------------- GEMM1 (fused x-conversion) + layer-1 attention scores -----
// Block tile: 64 rows x 256 cols, K-chunk = 32, 3-stage ring (R14 structure).
#define G1_SS     22016
#define G1_OFF_AH 0
#define G1_OFF_BH 5120
#define G1_SMEM   (3 * G1_SS)

__global__ __launch_bounds__(256, 2) void mma_gemm1(const float* __restrict__ x,
                                                    const float* __restrict__ ah, int M) {
    extern __shared__ __align__(16) char dsm[];
    uint32_t sbase = (uint32_t)__cvta_generic_to_shared(dsm);

    int tid = threadIdx.x;
    int lane = tid & 31, warp = tid >> 5;
    int warpM = (warp >> 2) * 32;
    int warpN = (warp & 3) * 64;
    int blockRow = blockIdx.x * 64;

    int arow = tid >> 2, ak8 = (tid & 3) * 8;
    int agr = blockRow + arow;
    bool aok = (agr < M);
    const float* gA = x + (size_t)agr * NFEAT + ak8;

    uint32_t sBb = sbase + G1_OFF_BH;

    float acc[2][8][4];
#pragma unroll
    for (int a = 0; a < 2; a++)
#pragma unroll
        for (int b = 0; b < 8; b++)
#pragma unroll
            for (int c = 0; c < 4; c++) acc[a][b][c] = 0.f;

    float areg[8];
    auto ldgA = [&](int kc) {
        if (aok) {
            float4 v0 = *(const float4*)(gA + kc * 32);
            float4 v1 = *(const float4*)(gA + kc * 32 + 4);
            areg[0] = v0.x; areg[1] = v0.y; areg[2] = v0.z; areg[3] = v0.w;
            areg[4] = v1.x; areg[5] = v1.y; areg[6] = v1.z; areg[7] = v1.w;
        } else {
#pragma unroll
            for (int j = 0; j < 8; j++) areg[j] = 0.f;
        }
    };
    auto stsA = [&](int st) {
        __half h8[8];
#pragma unroll
        for (int j = 0; j < 8; j++) h8[j] = __float2half_rn(areg[j]);
        *(uint4*)(dsm + st * G1_SS + G1_OFF_AH + (arow * 40 + ak8) * 2) = *(uint4*)h8;
    };
    auto cpB = [&](int kc, int st) {
        int k0 = kc * 32;
#pragma unroll
        for (int it = 0; it < 4; it++) {
            int chunk = it * 256 + tid;
            int brow = chunk >> 5, bc8 = (chunk & 31) * 8;
            cpa16(sBb + st * G1_SS + (uint32_t)(brow * 264 + bc8) * 2,
                  g_Whi + (size_t)(k0 + brow) * HCAT + bc8);
        }
        asm volatile("cp.async.commit_group;");
    };

    ldgA(0);
    cpB(0, 0);
    cpB(1, 1);

    int laneRow = lane & 15;
    int laneSeg = (lane >> 4) * 8;

#pragma unroll
    for (int c = 0; c < 8; c++) {
        int cur = c % 3;
        stsA(cur);
        if (c < 7) ldgA(c + 1);
        if (c + 2 < 8) cpB(c + 2, (c + 2) % 3);
        if (c <= 5)      { asm volatile("cp.async.wait_group 2;"); }
        else if (c == 6) { asm volatile("cp.async.wait_group 1;"); }
        else             { asm volatile("cp.async.wait_group 0;"); }
        __syncthreads();

        uint32_t sb = sbase + cur * G1_SS;
#pragma unroll
        for (int kk = 0; kk < 32; kk += 16) {
            uint32_t ahf[2][4];
#pragma unroll
            for (int mt = 0; mt < 2; mt++) {
                uint32_t ad = sb + G1_OFF_AH +
                    2u * (uint32_t)((warpM + mt * 16 + laneRow) * 40 + kk + laneSeg);
                ldsm4(ahf[mt][0], ahf[mt][1], ahf[mt][2], ahf[mt][3], ad);
            }
#pragma unroll
            for (int nt = 0; nt < 4; nt++) {
                uint32_t bd = sb + G1_OFF_BH +
                    2u * (uint32_t)((kk + laneRow) * 264 + warpN + nt * 16 + laneSeg);
                uint32_t bh0, bh1, bh2, bh3;
                ldsm4t(bh0, bh1, bh2, bh3, bd);
#pragma unroll
                for (int mt = 0; mt < 2; mt++) {
                    mma16816(acc[mt][2 * nt],     ahf[mt], bh0, bh1);
                    mma16816(acc[mt][2 * nt + 1], ahf[mt], bh2, bh3);
                }
            }
        }
        __syncthreads();
    }

#pragma unroll
    for (int mt = 0; mt < 2; mt++) {
#pragma unroll
        for (int n8 = 0; n8 < 8; n8++) {
            int r = blockRow + warpM + mt * 16 + (lane >> 2);
            int cc = warpN + n8 * 8 + (lane & 3) * 2;
            __half2 p0 = __floats2half2_rn(acc[mt][n8][0], acc[mt][n8][1]);
            __half2 p1 = __floats2half2_rn(acc[mt][n8][2], acc[mt][n8][3]);
            *(__half2*)(g_hcat + (size_t)r * HCAT + cc) = p0;
            *(__half2*)(g_hcat + (size_t)(r + 8) * HCAT + cc) = p1;
        }
    }

    int hd = warpN >> 6;
    const float* aH = ah + hd * 128;
    float s_src[2][2] = {{0.f, 0.f}, {0.f, 0.f}};
    float s_dst[2][2] = {{0.f, 0.f}, {0.f, 0.f}};
#pragma unroll
    for (int n8 = 0; n8 < 8; n8++) {
        int cc = n8 * 8 + (lane & 3) * 2;
        float a0 = __ldg(aH + cc),      a1 = __ldg(aH + cc + 1);
        float b0 = __ldg(aH + 64 + cc), b1 = __ldg(aH + 64 + cc + 1);
#pragma unroll
        for (int mt = 0; mt < 2; mt++) {
            s_src[mt][0] += acc[mt][n8][0] * a0 + acc[mt][n8][1] * a1;
            s_dst[mt][0] += acc[mt][n8][0] * b0 + acc[mt][n8][1] * b1;
            s_src[mt][1] += acc[mt][n8][2] * a0 + acc[mt][n8][3] * a1;
            s_dst[mt][1] += acc[mt][n8][2] * b0 + acc[mt][n8][3] * b1;
        }
    }
#pragma unroll
    for (int mt = 0; mt < 2; mt++)
#pragma unroll
        for (int hh = 0; hh < 2; hh++) {
            float s1 = s_src[mt][hh], s2 = s_dst[mt][hh];
            s1 += __shfl_xor_sync(0xffffffffu, s1, 1);
            s1 += __shfl_xor_sync(0xffffffffu, s1, 2);
            s2 += __shfl_xor_sync(0xffffffffu, s2, 1);
            s2 += __shfl_xor_sync(0xffffffffu, s2, 2);
            if ((lane & 3) == 0) {
                int r = blockRow + warpM + mt * 16 + (lane >> 2) + hh * 8;
                g_ss[r * NHEADS + hd] = s1;
                g_sd[r * NHEADS + hd] = s2;
            }
        }
}

// ---------------- layer-1 aggregation (warp per src node, fp16 gather) -----
__device__ __forceinline__ void accum8(float* acc, uint4 r, float e) {
    float2 f0 = __half22float2(*(__half2*)&r.x);
    float2 f1 = __half22float2(*(__half2*)&r.y);
    float2 f2 = __half22float2(*(__half2*)&r.z);
    float2 f3 = __half22float2(*(__half2*)&r.w);
    acc[0] += e * f0.x; acc[1] += e * f0.y;
    acc[2] += e * f1.x; acc[3] += e * f1.y;
    acc[4] += e * f2.x; acc[5] += e * f2.y;
    acc[6] += e * f3.x; acc[7] += e * f3.y;
}

__global__ void agg1_kernel(int n) {
    int w = (blockIdx.x * blockDim.x + threadIdx.x) >> 5;
    int lane = threadIdx.x & 31;
    if (w >= n) return;
    int start = g_rowptr[w];
    int end = g_rowptr[w + 1];
    int hd = lane >> 3;
    int eidx = lane >> 2;
    int hidx = lane & 3;
    float ss_h = g_ss[w * NHEADS + hidx];
    float acc[8] = {0.f, 0.f, 0.f, 0.f, 0.f, 0.f, 0.f, 0.f};
    float rs32 = 0.f;
    const uint4* hp = (const uint4*)g_hcat;

    int idx = start;
    for (; idx + 8 <= end; idx += 8) {
        int d0 = __ldg(g_col + idx),     d1 = __ldg(g_col + idx + 1);
        int d2 = __ldg(g_col + idx + 2), d3 = __ldg(g_col + idx + 3);
        int d4 = __ldg(g_col + idx + 4), d5 = __ldg(g_col + idx + 5);
        int d6 = __ldg(g_col + idx + 6), d7 = __ldg(g_col + idx + 7);
        int dsel;
        switch (eidx) {
            case 0: dsel = d0; break; case 1: dsel = d1; break;
            case 2: dsel = d2; break; case 3: dsel = d3; break;
            case 4: dsel = d4; break; case 5: dsel = d5; break;
            case 6: dsel = d6; break; default: dsel = d7; break;
        }
        float ev = __expf(-lrelu(ss_h + __ldg(g_sd + dsel * NHEADS + hidx)));
        rs32 += ev;
        uint4 r0 = __ldg(hp + (size_t)d0 * 32 + lane);
        uint4 r1 = __ldg(hp + (size_t)d1 * 32 + lane);
        uint4 r2 = __ldg(hp + (size_t)d2 * 32 + lane);
        uint4 r3 = __ldg(hp + (size_t)d3 * 32 + lane);
        uint4 r4 = __ldg(hp + (size_t)d4 * 32 + lane);
        uint4 r5 = __ldg(hp + (size_t)d5 * 32 + lane);
        uint4 r6 = __ldg(hp + (size_t)d6 * 32 + lane);
        uint4 r7 = __ldg(hp + (size_t)d7 * 32 + lane);
        accum8(acc, r0, __shfl_sync(0xffffffffu, ev, 0 * 4 + hd));
        accum8(acc, r1, __shfl_sync(0xffffffffu, ev, 1 * 4 + hd));
        accum8(acc, r2, __shfl_sync(0xffffffffu, ev, 2 * 4 + hd));
        accum8(acc, r3, __shfl_sync(0xffffffffu, ev, 3 * 4 + hd));
        accum8(acc, r4, __shfl_sync(0xffffffffu, ev, 4 * 4 + hd));
        accum8(acc, r5, __shfl_sync(0xffffffffu, ev, 5 * 4 + hd));
        accum8(acc, r6, __shfl_sync(0xffffffffu, ev, 6 * 4 + hd));
        accum8(acc, r7, __shfl_sync(0xffffffffu, ev, 7 * 4 + hd));
    }
    for (; idx < end; idx++) {
        int d = __ldg(g_col + idx);
        float ev = 0.f;
        if (lane < 4) {
            ev = __expf(-lrelu(ss_h + __ldg(g_sd + d * NHEADS + hidx)));
            rs32 += ev;
        }
        uint4 r = __ldg(hp + (size_t)d * 32 + lane);
        accum8(acc, r, __shfl_sync(0xffffffffu, ev, hd));
    }

    rs32 += __shfl_xor_sync(0xffffffffu, rs32, 4);
    rs32 += __shfl_xor_sync(0xffffffffu, rs32, 8);
    rs32 += __shfl_xor_sync(0xffffffffu, rs32, 16);
    float rs = __shfl_sync(0xffffffffu, rs32, hd);
    float inv = 1.f / rs;

    __half hi8[8];
#pragma unroll
    for (int j = 0; j < 8; j++) {
        hi8[j] = __float2half_rn(eluf(acc[j] * inv));
    }
    *(uint4*)(g_x1hi + (size_t)w * HCAT + lane * 8) = *(uint4*)hi8;
}

// ---------------- GEMM2 (tensor cores) + fused layer-2 scores ---------------
#define G2_OFF_AH 0
#define G2_OFF_BH 67584
#define G2_SMEM   88064

__global__ __launch_bounds__(256) void mma_gemm2(const float* __restrict__ aout) {
    extern __shared__ __align__(16) char dsm[];
    uint32_t sb = (uint32_t)__cvta_generic_to_shared(dsm);
    int tid = threadIdx.x;
    int blockRow = blockIdx.x * 128;

#pragma unroll
    for (int it = 0; it < 16; it++) {
        int chunk = it * 256 + tid;
        int row = chunk >> 5, col8 = (chunk & 31) * 8;
        size_t goff = (size_t)(blockRow + row) * HCAT + col8;
        uint32_t sa = sb + G2_OFF_AH + (uint32_t)(row * 264 + col8) * 2;
        cpa16(sa, g_x1hi + goff);
    }
#pragma unroll
    for (int it = 0; it < 4; it++) {
        int chunk = it * 256 + tid;
        int row = chunk >> 2, col8 = (chunk & 3) * 8;
        uint32_t sB = sb + G2_OFF_BH + (uint32_t)(row * 40 + col8) * 2;
        cpa16(sB, g_W2hi + row * NCLASS + col8);
    }
    asm volatile("cp.async.commit_group;");
    asm volatile("cp.async.wait_group 0;");
    __syncthreads();

    int warp = tid >> 5, lane = tid & 31;
    int laneRow = lane & 15, laneSeg = (lane >> 4) * 8;
    float acc[4][4];
#pragma unroll
    for (int a = 0; a < 4; a++)
#pragma unroll
        for (int c = 0; c < 4; c++) acc[a][c] = 0.f;

#pragma unroll
    for (int kk = 0; kk < 256; kk += 16) {
        uint32_t ad = sb + G2_OFF_AH + 2u * (uint32_t)((warp * 16 + laneRow) * 264 + kk + laneSeg);
        uint32_t ahf[4];
        ldsm4(ahf[0], ahf[1], ahf[2], ahf[3], ad);
#pragma unroll
        for (int nt = 0; nt < 2; nt++) {
            uint32_t bd = sb + G2_OFF_BH + 2u * (uint32_t)((kk + laneRow) * 40 + nt * 16 + laneSeg);
            uint32_t bh0, bh1, bh2, bh3;
            ldsm4t(bh0, bh1, bh2, bh3, bd);
            mma16816(acc[2 * nt],     ahf, bh0, bh1);
            mma16816(acc[2 * nt + 1], ahf, bh2, bh3);
        }
    }

    int r0 = blockRow + warp * 16 + (lane >> 2);
    float s1[2] = {0.f, 0.f}, s2[2] = {0.f, 0.f};
#pragma unroll
    for (int n8 = 0; n8 < 4; n8++) {
        int cc = n8 * 8 + (lane & 3) * 2;
        float a0 = __ldg(aout + cc),      a1 = __ldg(aout + cc + 1);
        float b0 = __ldg(aout + 32 + cc), b1 = __ldg(aout + 32 + cc + 1);
        *(__half2*)(g_h2h + (size_t)r0 * NCLASS + cc) = __floats2half2_rn(acc[n8][0], acc[n8][1]);
        *(__half2*)(g_h2h + (size_t)(r0 + 8) * NCLASS + cc) = __floats2half2_rn(acc[n8][2], acc[n8][3]);
        s1[0] += acc[n8][0] * a0 + acc[n8][1] * a1;
        s2[0] += acc[n8][0] * b0 + acc[n8][1] * b1;
        s1[1] += acc[n8][2] * a0 + acc[n8][3] * a1;
        s2[1] += acc[n8][2] * b0 + acc[n8][3] * b1;
    }
#pragma unroll
    for (int hh = 0; hh < 2; hh++) {
        float p1 = s1[hh], p2 = s2[hh];
        p1 += __shfl_xor_sync(0xffffffffu, p1, 1);
        p1 += __shfl_xor_sync(0xffffffffu, p1, 2);
        p2 += __shfl_xor_sync(0xffffffffu, p2, 1);
        p2 += __shfl_xor_sync(0xffffffffu, p2, 2);
        if ((lane & 3) == 0) {
            g_ss2[r0 + hh * 8] = p1;
            g_sd2[r0 + hh * 8] = p2;
        }
    }
}

// ---------------- layer-2 aggregation + elu + log_softmax ------------------
__global__ void agg2_kernel(float* __restrict__ out, int n) {
    int w = (blockIdx.x * blockDim.x + threadIdx.x) >> 5;
    int lane = threadIdx.x & 31;
    if (w >= n) return;
    int start = g_rowptr[w];
    int end = g_rowptr[w + 1];
    float ssn = g_ss2[w];
    int myoff = lane >> 4;
    int cpos = (lane & 15) * 2;
    float ax = 0.f, ay = 0.f, rs = 0.f;

    int idx = start;
    for (; idx + 16 <= end; idx += 16) {
        int d[8];
#pragma unroll
        for (int p = 0; p < 8; p++) d[p] = __ldg(g_col + idx + p * 2 + myoff);
        float ev[8];
#pragma unroll
        for (int p = 0; p < 8; p++) ev[p] = __expf(-lrelu(ssn + __ldg(g_sd2 + d[p])));
        float2 hv[8];
#pragma unroll
        for (int p = 0; p < 8; p++)
            hv[p] = __half22float2(__ldg((const __half2*)(g_h2h + (size_t)d[p] * NCLASS + cpos)));
#pragma unroll
        for (int p = 0; p < 8; p++) {
            ax += ev[p] * hv[p].x;
            ay += ev[p] * hv[p].y;
            rs += ev[p];
        }
    }
    for (; idx + 2 <= end; idx += 2) {
        int d = __ldg(g_col + idx + myoff);
        float ev = __expf(-lrelu(ssn + __ldg(g_sd2 + d)));
        float2 hv = __half22float2(__ldg((const __half2*)(g_h2h + (size_t)d * NCLASS + cpos)));
        ax += ev * hv.x; ay += ev * hv.y; rs += ev;
    }
    if (idx < end) {
        int d = __ldg(g_col + idx);
        if (lane < 16) {
            float ev = __expf(-lrelu(ssn + __ldg(g_sd2 + d)));
            float2 hv = __half22float2(__ldg((const __half2*)(g_h2h + (size_t)d * NCLASS + cpos)));
            ax += ev * hv.x; ay += ev * hv.y; rs += ev;
        }
    }

    ax += __shfl_xor_sync(0xffffffffu, ax, 16);
    ay += __shfl_xor_sync(0xffffffffu, ay, 16);
    rs += __shfl_xor_sync(0xffffffffu, rs, 16);

    float inv = 1.f / rs;
    float vx = eluf(ax * inv);
    float vy = eluf(ay * inv);
    float m = fmaxf(vx, vy);
#pragma unroll
    for (int off = 8; off; off >>= 1) m = fmaxf(m, __shfl_xor_sync(0xffffffffu, m, off));
    float sum = __expf(vx - m) + __expf(vy - m);
#pragma unroll
    for (int off = 8; off; off >>= 1) sum += __shfl_xor_sync(0xffffffffu, sum, off);
    float ls = __logf(sum);
    if (lane < 16) {
        *(float2*)(out + (size_t)w * NCLASS + cpos) = make_float2(vx - m - ls, vy - m - ls);
    }
}

// ---------------- launch ----------------------------------------------------
extern "C" void kernel_launch(void* const* d_in, const int* in_sizes, int n_in,
                              void* d_out, int out_size) {
    const float* x = (const float*)d_in[0];
    const int* edge = (const int*)d_in[1];
    const float* W_heads = (const float*)d_in[2];
    const float* a_heads = (const float*)d_in[3];
    const float* W_out = (const float*)d_in[4];
    const float* a_out = (const float*)d_in[5];
    float* out = (float*)d_out;

    int n = in_sizes[0] / NFEAT;       // 100000
    int e = in_sizes[1] / 2;           // 1600000
    const int* src = edge;
    const int* dst = edge + e;

    static cudaStream_t s_side = nullptr;
    static cudaEvent_t ev_fork = nullptr, ev_join = nullptr;
    if (s_side == nullptr) {
        cudaFuncSetAttribute(mma_gemm1, cudaFuncAttributeMaxDynamicSharedMemorySize, G1_SMEM);
        cudaFuncSetAttribute(mma_gemm2, cudaFuncAttributeMaxDynamicSharedMemorySize, G2_SMEM);
        cudaStreamCreateWithFlags(&s_side, cudaStreamNonBlocking);
        cudaEventCreateWithFlags(&ev_fork, cudaEventDisableTiming);
        cudaEventCreateWithFlags(&ev_join, cudaEventDisableTiming);
    }

    // fork side stream immediately (CSR monolith has no deps on main work)
    cudaEventRecord(ev_fork, 0);
    cudaStreamWaitEvent(s_side, ev_fork, 0);
    csr_mono<<<CSR_BLOCKS, 1024, 0, s_side>>>(src, dst, n, e);         // launch 1
    cudaEventRecord(ev_join, s_side);

    // main stream: W conversion, then fused-conversion GEMM1
    int prep_elems = NHEADS * NFEAT * NHID;
    prep_kernel<<<(prep_elems + 255) / 256, 256>>>(W_heads, W_out);    // launch 2
    mma_gemm1<<<(n + 63) / 64, 256, G1_SMEM>>>(x, a_heads, n);         // launch 3

    // join: aggregation needs CSR
    cudaStreamWaitEvent(0, ev_join, 0);

    int nwarp_blocks = (n + 7) / 8;
    agg1_kernel<<<nwarp_blocks, 256>>>(n);                             // launch 4 (ncu slot)
    mma_gemm2<<<(n + 127) / 128, 256, G2_SMEM>>>(a_out);               // launch 5
    agg2_kernel<<<nwarp_blocks, 256>>>(out, n);                        // launch 6
}

// round 16
// speedup vs baseline: 1.0785x; 1.0785x over previous
#include <cuda_runtime.h>
#include <cuda_bf16.h>
#include <cuda_fp16.h>
#include <cstdint>

// Problem constants (match reference)
#define NN 100000
#define EE 1600000
#define NFEAT 256
#define NHID 64
#define NHEADS 4
#define HCAT 256   // NHEADS*NHID
#define NCLASS 32
#define ALPHA 0.2f

#define MPAD 128   // row padding so GEMMs need no bounds checks

// ---------------- scratch (device globals; no allocation at runtime) -------
__device__ __half g_Whi[NFEAT * HCAT];
__device__ __half g_W2hi[HCAT * NCLASS];
__device__ __half g_hcat[(size_t)(NN + MPAD) * HCAT];     // layer-1 features (fp16)
__device__ __half g_x1hi[(size_t)(NN + MPAD) * HCAT];
__device__ float g_ss[(NN + MPAD) * NHEADS];
__device__ float g_sd[(NN + MPAD) * NHEADS];
__device__ int   g_deg[NN];
__device__ int   g_rowptr[NN + 1];
__device__ int   g_cursor[NN];
__device__ int   g_col[EE];
__device__ int   g_blocksums[1024];
__device__ __half g_h2h[(size_t)(NN + MPAD) * NCLASS];    // layer-2 features (fp16)
__device__ float g_ss2[NN + MPAD];
__device__ float g_sd2[NN + MPAD];

__device__ __forceinline__ float eluf(float v) { return v > 0.f ? v : expm1f(v); }
__device__ __forceinline__ float lrelu(float v) { return v > 0.f ? v : ALPHA * v; }

// ---------------- prep: W_heads/W_out -> fp16, concat layout; zero deg ------
__global__ void prep_kernel(const float* __restrict__ Wh, const float* __restrict__ W2, int n) {
    int i = blockIdx.x * blockDim.x + threadIdx.x;
    if (i < NHEADS * NFEAT * NHID) {
        int h = i >> 14;
        int rem = i & 16383;
        int k = rem >> 6;
        int c = rem & 63;
        g_Whi[k * HCAT + (h << 6) + c] = __float2half_rn(Wh[i]);
    }
    if (i < HCAT * NCLASS) {
        g_W2hi[i] = __float2half_rn(W2[i]);
    }
    if (i < n) g_deg[i] = 0;
}

// ---------------- mma helpers -----------------------------------------------
__device__ __forceinline__ void ldsm4(uint32_t& r0, uint32_t& r1, uint32_t& r2, uint32_t& r3, uint32_t addr) {
    asm volatile("ldmatrix.sync.aligned.m8n8.x4.shared.b16 {%0,%1,%2,%3}, [%4];"
                 : "=r"(r0), "=r"(r1), "=r"(r2), "=r"(r3) : "r"(addr));
}
__device__ __forceinline__ void ldsm4t(uint32_t& r0, uint32_t& r1, uint32_t& r2, uint32_t& r3, uint32_t addr) {
    asm volatile("ldmatrix.sync.aligned.m8n8.x4.trans.shared.b16 {%0,%1,%2,%3}, [%4];"
                 : "=r"(r0), "=r"(r1), "=r"(r2), "=r"(r3) : "r"(addr));
}
__device__ __forceinline__ void mma16816(float* c, const uint32_t* a, uint32_t b0, uint32_t b1) {
    asm volatile("mma.sync.aligned.m16n8k16.row.col.f32.f16.f16.f32 "
                 "{%0,%1,%2,%3}, {%4,%5,%6,%7}, {%8,%9}, {%0,%1,%2,%3};"
                 : "+f"(c[0]), "+f"(c[1]), "+f"(c[2]), "+f"(c[3])
                 : "r"(a[0]), "r"(a[1]), "r"(a[2]), "r"(a[3]), "r"(b0), "r"(b1));
}
__device__ __forceinline__ void cpa16(uint32_t s, const void* g) {
    asm volatile("cp.async.cg.shared.global [%0], [%1], 16;" :: "r"(s), "l"(g));
}

// ---------------- GEMM1 (fused x-conversion) + layer-1 attention scores -----
// Block tile: 64 rows x 256 cols, K-chunk = 32, 3-stage ring (R14 structure).
#define G1_SS     22016
#define G1_OFF_AH 0
#define G1_OFF_BH 5120
#define G1_SMEM   (3 * G1_SS)

__global__ __launch_bounds__(256, 2) void mma_gemm1(const float* __restrict__ x,
                                                    const float* __restrict__ ah, int M) {
    extern __shared__ __align__(16) char dsm[];
    uint32_t sbase = (uint32_t)__cvta_generic_to_shared(dsm);

    int tid = threadIdx.x;
    int lane = tid & 31, warp = tid >> 5;
    int warpM = (warp >> 2) * 32;
    int warpN = (warp & 3) * 64;
    int blockRow = blockIdx.x * 64;

    int arow = tid >> 2, ak8 = (tid & 3) * 8;
    int agr = blockRow + arow;
    bool aok = (agr < M);
    const float* gA = x + (size_t)agr * NFEAT + ak8;

    uint32_t sBb = sbase + G1_OFF_BH;

    float acc[2][8][4];
#pragma unroll
    for (int a = 0; a < 2; a++)
#pragma unroll
        for (int b = 0; b < 8; b++)
#pragma unroll
            for (int c = 0; c < 4; c++) acc[a][b][c] = 0.f;

    float areg[8];
    auto ldgA = [&](int kc) {
        if (aok) {
            float4 v0 = *(const float4*)(gA + kc * 32);
            float4 v1 = *(const float4*)(gA + kc * 32 + 4);
            areg[0] = v0.x; areg[1] = v0.y; areg[2] = v0.z; areg[3] = v0.w;
            areg[4] = v1.x; areg[5] = v1.y; areg[6] = v1.z; areg[7] = v1.w;
        } else {
#pragma unroll
            for (int j = 0; j < 8; j++) areg[j] = 0.f;
        }
    };
    auto stsA = [&](int st) {
        __half h8[8];
#pragma unroll
        for (int j = 0; j < 8; j++) h8[j] = __float2half_rn(areg[j]);
        *(uint4*)(dsm + st * G1_SS + G1_OFF_AH + (arow * 40 + ak8) * 2) = *(uint4*)h8;
    };
    auto cpB = [&](int kc, int st) {
        int k0 = kc * 32;
#pragma unroll
        for (int it = 0; it < 4; it++) {
            int chunk = it * 256 + tid;
            int brow = chunk >> 5, bc8 = (chunk & 31) * 8;
            cpa16(sBb + st * G1_SS + (uint32_t)(brow * 264 + bc8) * 2,
                  g_Whi + (size_t)(k0 + brow) * HCAT + bc8);
        }
        asm volatile("cp.async.commit_group;");
    };

    ldgA(0);
    cpB(0, 0);
    cpB(1, 1);

    int laneRow = lane & 15;
    int laneSeg = (lane >> 4) * 8;

#pragma unroll
    for (int c = 0; c < 8; c++) {
        int cur = c % 3;
        stsA(cur);
        if (c < 7) ldgA(c + 1);
        if (c + 2 < 8) cpB(c + 2, (c + 2) % 3);
        if (c <= 5)      { asm volatile("cp.async.wait_group 2;"); }
        else if (c == 6) { asm volatile("cp.async.wait_group 1;"); }
        else             { asm volatile("cp.async.wait_group 0;"); }
        __syncthreads();

        uint32_t sb = sbase + cur * G1_SS;
#pragma unroll
        for (int kk = 0; kk < 32; kk += 16) {
            uint32_t ahf[2][4];
#pragma unroll
            for (int mt = 0; mt < 2; mt++) {
                uint32_t ad = sb + G1_OFF_AH +
                    2u * (uint32_t)((warpM + mt * 16 + laneRow) * 40 + kk + laneSeg);
                ldsm4(ahf[mt][0], ahf[mt][1], ahf[mt][2], ahf[mt][3], ad);
            }
#pragma unroll
            for (int nt = 0; nt < 4; nt++) {
                uint32_t bd = sb + G1_OFF_BH +
                    2u * (uint32_t)((kk + laneRow) * 264 + warpN + nt * 16 + laneSeg);
                uint32_t bh0, bh1, bh2, bh3;
                ldsm4t(bh0, bh1, bh2, bh3, bd);
#pragma unroll
                for (int mt = 0; mt < 2; mt++) {
                    mma16816(acc[mt][2 * nt],     ahf[mt], bh0, bh1);
                    mma16816(acc[mt][2 * nt + 1], ahf[mt], bh2, bh3);
                }
            }
        }
        __syncthreads();
    }

#pragma unroll
    for (int mt = 0; mt < 2; mt++) {
#pragma unroll
        for (int n8 = 0; n8 < 8; n8++) {
            int r = blockRow + warpM + mt * 16 + (lane >> 2);
            int cc = warpN + n8 * 8 + (lane & 3) * 2;
            __half2 p0 = __floats2half2_rn(acc[mt][n8][0], acc[mt][n8][1]);
            __half2 p1 = __floats2half2_rn(acc[mt][n8][2], acc[mt][n8][3]);
            *(__half2*)(g_hcat + (size_t)r * HCAT + cc) = p0;
            *(__half2*)(g_hcat + (size_t)(r + 8) * HCAT + cc) = p1;
        }
    }

    int hd = warpN >> 6;
    const float* aH = ah + hd * 128;
    float s_src[2][2] = {{0.f, 0.f}, {0.f, 0.f}};
    float s_dst[2][2] = {{0.f, 0.f}, {0.f, 0.f}};
#pragma unroll
    for (int n8 = 0; n8 < 8; n8++) {
        int cc = n8 * 8 + (lane & 3) * 2;
        float a0 = __ldg(aH + cc),      a1 = __ldg(aH + cc + 1);
        float b0 = __ldg(aH + 64 + cc), b1 = __ldg(aH + 64 + cc + 1);
#pragma unroll
        for (int mt = 0; mt < 2; mt++) {
            s_src[mt][0] += acc[mt][n8][0] * a0 + acc[mt][n8][1] * a1;
            s_dst[mt][0] += acc[mt][n8][0] * b0 + acc[mt][n8][1] * b1;
            s_src[mt][1] += acc[mt][n8][2] * a0 + acc[mt][n8][3] * a1;
            s_dst[mt][1] += acc[mt][n8][2] * b0 + acc[mt][n8][3] * b1;
        }
    }
#pragma unroll
    for (int mt = 0; mt < 2; mt++)
#pragma unroll
        for (int hh = 0; hh < 2; hh++) {
            float s1 = s_src[mt][hh], s2 = s_dst[mt][hh];
            s1 += __shfl_xor_sync(0xffffffffu, s1, 1);
            s1 += __shfl_xor_sync(0xffffffffu, s1, 2);
            s2 += __shfl_xor_sync(0xffffffffu, s2, 1);
            s2 += __shfl_xor_sync(0xffffffffu, s2, 2);
            if ((lane & 3) == 0) {
                int r = blockRow + warpM + mt * 16 + (lane >> 2) + hh * 8;
                g_ss[r * NHEADS + hd] = s1;
                g_sd[r * NHEADS + hd] = s2;
            }
        }
}

// ---------------- CSR construction (5-kernel fork, R14 structure) ----------
__global__ void hist_kernel(const int* __restrict__ src, int e) {
    int i = blockIdx.x * blockDim.x + threadIdx.x;
    if (i < e) atomicAdd(&g_deg[src[i]], 1);
}

__global__ __launch_bounds__(1024) void scan1_kernel(int n) {
    __shared__ int s[1024];
    int t = threadIdx.x;
    int idx = blockIdx.x * 1024 + t;
    int v = (idx < n) ? g_deg[idx] : 0;
    s[t] = v;
    __syncthreads();
#pragma unroll
    for (int off = 1; off < 1024; off <<= 1) {
        int x = (t >= off) ? s[t - off] : 0;
        __syncthreads();
        s[t] += x;
        __syncthreads();
    }
    if (idx < n) g_rowptr[idx] = s[t] - v;
    if (t == 1023) g_blocksums[blockIdx.x] = s[1023];
}

__global__ __launch_bounds__(1024) void scan2_kernel(int nb) {
    __shared__ int s[1024];
    int t = threadIdx.x;
    int v = (t < nb) ? g_blocksums[t] : 0;
    s[t] = v;
    __syncthreads();
#pragma unroll
    for (int off = 1; off < 1024; off <<= 1) {
        int x = (t >= off) ? s[t - off] : 0;
        __syncthreads();
        s[t] += x;
        __syncthreads();
    }
    if (t < nb) g_blocksums[t] = s[t] - v;
}

__global__ void scan3_kernel(int n, int e) {
    int i = blockIdx.x * blockDim.x + threadIdx.x;
    if (i < n) {
        int r = g_rowptr[i] + g_blocksums[i >> 10];
        g_rowptr[i] = r;
        g_cursor[i] = r;
    }
    if (i == 0) g_rowptr[n] = e;
}

__global__ void scatter_kernel(const int* __restrict__ src, const int* __restrict__ dst, int e) {
    int i = blockIdx.x * blockDim.x + threadIdx.x;
    if (i < e) {
        int s = src[i];
        int p = atomicAdd(&g_cursor[s], 1);
        g_col[p] = dst[i];
    }
}

// ---------------- layer-1 aggregation (warp per node, half2 inner accum) ---
__device__ __forceinline__ void accum8(float* acc, uint4 r, float e) {
    float2 f0 = __half22float2(*(__half2*)&r.x);
    float2 f1 = __half22float2(*(__half2*)&r.y);
    float2 f2 = __half22float2(*(__half2*)&r.z);
    float2 f3 = __half22float2(*(__half2*)&r.w);
    acc[0] += e * f0.x; acc[1] += e * f0.y;
    acc[2] += e * f1.x; acc[3] += e * f1.y;
    acc[4] += e * f2.x; acc[5] += e * f2.y;
    acc[6] += e * f3.x; acc[7] += e * f3.y;
}

__device__ __forceinline__ void haccum(__half2* ah, uint4 r, __half2 e2) {
    ah[0] = __hfma2(e2, *(__half2*)&r.x, ah[0]);
    ah[1] = __hfma2(e2, *(__half2*)&r.y, ah[1]);
    ah[2] = __hfma2(e2, *(__half2*)&r.z, ah[2]);
    ah[3] = __hfma2(e2, *(__half2*)&r.w, ah[3]);
}

__global__ void agg1_kernel(int n) {
    int w = (blockIdx.x * blockDim.x + threadIdx.x) >> 5;
    int lane = threadIdx.x & 31;
    if (w >= n) return;
    int start = g_rowptr[w];
    int end = g_rowptr[w + 1];
    int hd = lane >> 3;
    int eidx = lane >> 2;
    int hidx = lane & 3;
    float ss_h = g_ss[w * NHEADS + hidx];
    float acc[8] = {0.f, 0.f, 0.f, 0.f, 0.f, 0.f, 0.f, 0.f};
    float rs32 = 0.f;
    const uint4* hp = (const uint4*)g_hcat;
    const __half2 hz = __float2half2_rn(0.f);

    int idx = start;
    for (; idx + 8 <= end; idx += 8) {
        int d0 = __ldg(g_col + idx),     d1 = __ldg(g_col + idx + 1);
        int d2 = __ldg(g_col + idx + 2), d3 = __ldg(g_col + idx + 3);
        int d4 = __ldg(g_col + idx + 4), d5 = __ldg(g_col + idx + 5);
        int d6 = __ldg(g_col + idx + 6), d7 = __ldg(g_col + idx + 7);
        int dsel;
        switch (eidx) {
            case 0: dsel = d0; break; case 1: dsel = d1; break;
            case 2: dsel = d2; break; case 3: dsel = d3; break;
            case 4: dsel = d4; break; case 5: dsel = d5; break;
            case 6: dsel = d6; break; default: dsel = d7; break;
        }
        float ev = __expf(-lrelu(ss_h + __ldg(g_sd + dsel * NHEADS + hidx)));
        rs32 += ev;
        uint4 r0 = __ldg(hp + (size_t)d0 * 32 + lane);
        uint4 r1 = __ldg(hp + (size_t)d1 * 32 + lane);
        uint4 r2 = __ldg(hp + (size_t)d2 * 32 + lane);
        uint4 r3 = __ldg(hp + (size_t)d3 * 32 + lane);
        uint4 r4 = __ldg(hp + (size_t)d4 * 32 + lane);
        uint4 r5 = __ldg(hp + (size_t)d5 * 32 + lane);
        uint4 r6 = __ldg(hp + (size_t)d6 * 32 + lane);
        uint4 r7 = __ldg(hp + (size_t)d7 * 32 + lane);
        // half2 inner accumulation: 4 HFMA2 per edge instead of 8 F2F + 8 FFMA
        __half2 ah[4] = {hz, hz, hz, hz};
        haccum(ah, r0, __float2half2_rn(__shfl_sync(0xffffffffu, ev, 0 * 4 + hd)));
        haccum(ah, r1, __float2half2_rn(__shfl_sync(0xffffffffu, ev, 1 * 4 + hd)));
        haccum(ah, r2, __float2half2_rn(__shfl_sync(0xffffffffu, ev, 2 * 4 + hd)));
        haccum(ah, r3, __float2half2_rn(__shfl_sync(0xffffffffu, ev, 3 * 4 + hd)));
        haccum(ah, r4, __float2half2_rn(__shfl_sync(0xffffffffu, ev, 4 * 4 + hd)));
        haccum(ah, r5, __float2half2_rn(__shfl_sync(0xffffffffu, ev, 5 * 4 + hd)));
        haccum(ah, r6, __float2half2_rn(__shfl_sync(0xffffffffu, ev, 6 * 4 + hd)));
        haccum(ah, r7, __float2half2_rn(__shfl_sync(0xffffffffu, ev, 7 * 4 + hd)));
        float2 f0 = __half22float2(ah[0]);
        float2 f1 = __half22float2(ah[1]);
        float2 f2 = __half22float2(ah[2]);
        float2 f3 = __half22float2(ah[3]);
        acc[0] += f0.x; acc[1] += f0.y;
        acc[2] += f1.x; acc[3] += f1.y;
        acc[4] += f2.x; acc[5] += f2.y;
        acc[6] += f3.x; acc[7] += f3.y;
    }
    for (; idx < end; idx++) {
        int d = __ldg(g_col + idx);
        float ev = 0.f;
        if (lane < 4) {
            ev = __expf(-lrelu(ss_h + __ldg(g_sd + d * NHEADS + hidx)));
            rs32 += ev;
        }
        uint4 r = __ldg(hp + (size_t)d * 32 + lane);
        accum8(acc, r, __shfl_sync(0xffffffffu, ev, hd));
    }

    rs32 += __shfl_xor_sync(0xffffffffu, rs32, 4);
    rs32 += __shfl_xor_sync(0xffffffffu, rs32, 8);
    rs32 += __shfl_xor_sync(0xffffffffu, rs32, 16);
    float rs = __shfl_sync(0xffffffffu, rs32, hd);
    float inv = 1.f / rs;

    __half hi8[8];
#pragma unroll
    for (int j = 0; j < 8; j++) {
        hi8[j] = __float2half_rn(eluf(acc[j] * inv));
    }
    *(uint4*)(g_x1hi + (size_t)w * HCAT + lane * 8) = *(uint4*)hi8;
}

// ---------------- GEMM2 (tensor cores) + fused layer-2 scores ---------------
#define G2_OFF_AH 0
#define G2_OFF_BH 67584
#define G2_SMEM   88064

__global__ __launch_bounds__(256) void mma_gemm2(const float* __restrict__ aout) {
    extern __shared__ __align__(16) char dsm[];
    uint32_t sb = (uint32_t)__cvta_generic_to_shared(dsm);
    int tid = threadIdx.x;
    int blockRow = blockIdx.x * 128;

#pragma unroll
    for (int it = 0; it < 16; it++) {
        int chunk = it * 256 + tid;
        int row = chunk >> 5, col8 = (chunk & 31) * 8;
        size_t goff = (size_t)(blockRow + row) * HCAT + col8;
        uint32_t sa = sb + G2_OFF_AH + (uint32_t)(row * 264 + col8) * 2;
        cpa16(sa, g_x1hi + goff);
    }
#pragma unroll
    for (int it = 0; it < 4; it++) {
        int chunk = it * 256 + tid;
        int row = chunk >> 2, col8 = (chunk & 3) * 8;
        uint32_t sB = sb + G2_OFF_BH + (uint32_t)(row * 40 + col8) * 2;
        cpa16(sB, g_W2hi + row * NCLASS + col8);
    }
    asm volatile("cp.async.commit_group;");
    asm volatile("cp.async.wait_group 0;");
    __syncthreads();

    int warp = tid >> 5, lane = tid & 31;
    int laneRow = lane & 15, laneSeg = (lane >> 4) * 8;
    float acc[4][4];
#pragma unroll
    for (int a = 0; a < 4; a++)
#pragma unroll
        for (int c = 0; c < 4; c++) acc[a][c] = 0.f;

#pragma unroll
    for (int kk = 0; kk < 256; kk += 16) {
        uint32_t ad = sb + G2_OFF_AH + 2u * (uint32_t)((warp * 16 + laneRow) * 264 + kk + laneSeg);
        uint32_t ahf[4];
        ldsm4(ahf[0], ahf[1], ahf[2], ahf[3], ad);
#pragma unroll
        for (int nt = 0; nt < 2; nt++) {
            uint32_t bd = sb + G2_OFF_BH + 2u * (uint32_t)((kk + laneRow) * 40 + nt * 16 + laneSeg);
            uint32_t bh0, bh1, bh2, bh3;
            ldsm4t(bh0, bh1, bh2, bh3, bd);
            mma16816(acc[2 * nt],     ahf, bh0, bh1);
            mma16816(acc[2 * nt + 1], ahf, bh2, bh3);
        }
    }

    int r0 = blockRow + warp * 16 + (lane >> 2);
    float s1[2] = {0.f, 0.f}, s2[2] = {0.f, 0.f};
#pragma unroll
    for (int n8 = 0; n8 < 4; n8++) {
        int cc = n8 * 8 + (lane & 3) * 2;
        float a0 = __ldg(aout + cc),      a1 = __ldg(aout + cc + 1);
        float b0 = __ldg(aout + 32 + cc), b1 = __ldg(aout + 32 + cc + 1);
        *(__half2*)(g_h2h + (size_t)r0 * NCLASS + cc) = __floats2half2_rn(acc[n8][0], acc[n8][1]);
        *(__half2*)(g_h2h + (size_t)(r0 + 8) * NCLASS + cc) = __floats2half2_rn(acc[n8][2], acc[n8][3]);
        s1[0] += acc[n8][0] * a0 + acc[n8][1] * a1;
        s2[0] += acc[n8][0] * b0 + acc[n8][1] * b1;
        s1[1] += acc[n8][2] * a0 + acc[n8][3] * a1;
        s2[1] += acc[n8][2] * b0 + acc[n8][3] * b1;
    }
#pragma unroll
    for (int hh = 0; hh < 2; hh++) {
        float p1 = s1[hh], p2 = s2[hh];
        p1 += __shfl_xor_sync(0xffffffffu, p1, 1);
        p1 += __shfl_xor_sync(0xffffffffu, p1, 2);
        p2 += __shfl_xor_sync(0xffffffffu, p2, 1);
        p2 += __shfl_xor_sync(0xffffffffu, p2, 2);
        if ((lane & 3) == 0) {
            g_ss2[r0 + hh * 8] = p1;
            g_sd2[r0 + hh * 8] = p2;
        }
    }
}

// ---------------- layer-2 aggregation + elu + log_softmax ------------------
__global__ void agg2_kernel(float* __restrict__ out, int n) {
    int w = (blockIdx.x * blockDim.x + threadIdx.x) >> 5;
    int lane = threadIdx.x & 31;
    if (w >= n) return;
    int start = g_rowptr[w];
    int end = g_rowptr[w + 1];
    float ssn = g_ss2[w];
    int myoff = lane >> 4;
    int cpos = (lane & 15) * 2;
    float ax = 0.f, ay = 0.f, rs = 0.f;

    int idx = start;
    for (; idx + 16 <= end; idx += 16) {
        int d[8];
#pragma unroll
        for (int p = 0; p < 8; p++) d[p] = __ldg(g_col + idx + p * 2 + myoff);
        float ev[8];
#pragma unroll
        for (int p = 0; p < 8; p++) ev[p] = __expf(-lrelu(ssn + __ldg(g_sd2 + d[p])));
        float2 hv[8];
#pragma unroll
        for (int p = 0; p < 8; p++)
            hv[p] = __half22float2(__ldg((const __half2*)(g_h2h + (size_t)d[p] * NCLASS + cpos)));
#pragma unroll
        for (int p = 0; p < 8; p++) {
            ax += ev[p] * hv[p].x;
            ay += ev[p] * hv[p].y;
            rs += ev[p];
        }
    }
    for (; idx + 2 <= end; idx += 2) {
        int d = __ldg(g_col + idx + myoff);
        float ev = __expf(-lrelu(ssn + __ldg(g_sd2 + d)));
        float2 hv = __half22float2(__ldg((const __half2*)(g_h2h + (size_t)d * NCLASS + cpos)));
        ax += ev * hv.x; ay += ev * hv.y; rs += ev;
    }
    if (idx < end) {
        int d = __ldg(g_col + idx);
        if (lane < 16) {
            float ev = __expf(-lrelu(ssn + __ldg(g_sd2 + d)));
            float2 hv = __half22float2(__ldg((const __half2*)(g_h2h + (size_t)d * NCLASS + cpos)));
            ax += ev * hv.x; ay += ev * hv.y; rs += ev;
        }
    }

    ax += __shfl_xor_sync(0xffffffffu, ax, 16);
    ay += __shfl_xor_sync(0xffffffffu, ay, 16);
    rs += __shfl_xor_sync(0xffffffffu, rs, 16);

    float inv = 1.f / rs;
    float vx = eluf(ax * inv);
    float vy = eluf(ay * inv);
    float m = fmaxf(vx, vy);
#pragma unroll
    for (int off = 8; off; off >>= 1) m = fmaxf(m, __shfl_xor_sync(0xffffffffu, m, off));
    float sum = __expf(vx - m) + __expf(vy - m);
#pragma unroll
    for (int off = 8; off; off >>= 1) sum += __shfl_xor_sync(0xffffffffu, sum, off);
    float ls = __logf(sum);
    if (lane < 16) {
        *(float2*)(out + (size_t)w * NCLASS + cpos) = make_float2(vx - m - ls, vy - m - ls);
    }
}

// ---------------- launch ----------------------------------------------------
extern "C" void kernel_launch(void* const* d_in, const int* in_sizes, int n_in,
                              void* d_out, int out_size) {
    const float* x = (const float*)d_in[0];
    const int* edge = (const int*)d_in[1];
    const float* W_heads = (const float*)d_in[2];
    const float* a_heads = (const float*)d_in[3];
    const float* W_out = (const float*)d_in[4];
    const float* a_out = (const float*)d_in[5];
    float* out = (float*)d_out;

    int n = in_sizes[0] / NFEAT;       // 100000
    int e = in_sizes[1] / 2;           // 1600000
    const int* src = edge;
    const int* dst = edge + e;

    static cudaStream_t s_side = nullptr;
    static cudaEvent_t ev_fork = nullptr, ev_join = nullptr;
    if (s_side == nullptr) {
        cudaFuncSetAttribute(mma_gemm1, cudaFuncAttributeMaxDynamicSharedMemorySize, G1_SMEM);
        cudaFuncSetAttribute(mma_gemm2, cudaFuncAttributeMaxDynamicSharedMemorySize, G2_SMEM);
        cudaStreamCreateWithFlags(&s_side, cudaStreamNonBlocking);
        cudaEventCreateWithFlags(&ev_fork, cudaEventDisableTiming);
        cudaEventCreateWithFlags(&ev_join, cudaEventDisableTiming);
    }

    // prep (W conversion + deg zero) must precede fork (hist needs g_deg=0)
    int prep_elems = NHEADS * NFEAT * NHID;
    int prep_grid = ((prep_elems > n ? prep_elems : n) + 255) / 256;
    prep_kernel<<<prep_grid, 256>>>(W_heads, W_out, n);   // launch 1

    // fork: CSR construction on side stream, overlapped with GEMM1
    cudaEventRecord(ev_fork, 0);
    cudaStreamWaitEvent(s_side, ev_fork, 0);
    hist_kernel<<<(e + 255) / 256, 256, 0, s_side>>>(src, e);          // launch 2
    int nb = (n + 1023) / 1024;
    scan1_kernel<<<nb, 1024, 0, s_side>>>(n);                          // launch 3

    // main stream: fused-conversion GEMM1
    mma_gemm1<<<(n + 63) / 64, 256, G1_SMEM>>>(x, a_heads, n);         // launch 4

    scan2_kernel<<<1, 1024, 0, s_side>>>(nb);                          // launch 5
    scan3_kernel<<<(n + 255) / 256, 256, 0, s_side>>>(n, e);           // launch 6
    scatter_kernel<<<(e + 255) / 256, 256, 0, s_side>>>(src, dst, e);  // launch 7
    cudaEventRecord(ev_join, s_side);

    // join: aggregation needs CSR
    cudaStreamWaitEvent(0, ev_join, 0);

    int nwarp_blocks = (n + 7) / 8;
    agg1_kernel<<<nwarp_blocks, 256>>>(n);                             // launch 8
    mma_gemm2<<<(n + 127) / 128, 256, G2_SMEM>>>(a_out);               // launch 9
    agg2_kernel<<<nwarp_blocks, 256>>>(out, n);                        // launch 10
}

// round 17
// speedup vs baseline: 1.1485x; 1.0649x over previous
#include <cuda_runtime.h>
#include <cuda_bf16.h>
#include <cuda_fp16.h>
#include <cstdint>

// Problem constants (match reference)
#define NN 100000
#define EE 1600000
#define NFEAT 256
#define NHID 64
#define NHEADS 4
#define HCAT 256   // NHEADS*NHID
#define NCLASS 32
#define ALPHA 0.2f

#define MPAD 128   // row padding so GEMMs need no bounds checks

// ---------------- scratch (device globals; no allocation at runtime) -------
__device__ __half g_Whi[NFEAT * HCAT];
__device__ __half g_W2hi[HCAT * NCLASS];
__device__ __half g_hcat[(size_t)(NN + MPAD) * HCAT];     // layer-1 features (fp16)
__device__ __half g_x1hi[(size_t)(NN + MPAD) * HCAT];
__device__ float g_ss[(NN + MPAD) * NHEADS];
__device__ float g_sd[(NN + MPAD) * NHEADS];
__device__ int   g_deg[NN];
__device__ int   g_rowptr[NN + 1];
__device__ int   g_cursor[NN];
__device__ int   g_col[EE];
__device__ int   g_blocksums[1024];
__device__ __half g_h2h[(size_t)(NN + MPAD) * NCLASS];    // layer-2 features (fp16)
__device__ float g_ss2[NN + MPAD];
__device__ float g_sd2[NN + MPAD];

__device__ __forceinline__ float eluf(float v) { return v > 0.f ? v : expm1f(v); }
__device__ __forceinline__ float lrelu(float v) { return v > 0.f ? v : ALPHA * v; }

// ---------------- prep: W_heads/W_out -> fp16, concat layout; zero deg ------
__global__ void prep_kernel(const float* __restrict__ Wh, const float* __restrict__ W2, int n) {
    int i = blockIdx.x * blockDim.x + threadIdx.x;
    if (i < NHEADS * NFEAT * NHID) {
        int h = i >> 14;
        int rem = i & 16383;
        int k = rem >> 6;
        int c = rem & 63;
        g_Whi[k * HCAT + (h << 6) + c] = __float2half_rn(Wh[i]);
    }
    if (i < HCAT * NCLASS) {
        g_W2hi[i] = __float2half_rn(W2[i]);
    }
    if (i < n) g_deg[i] = 0;
}

// ---------------- mma helpers -----------------------------------------------
__device__ __forceinline__ void ldsm4(uint32_t& r0, uint32_t& r1, uint32_t& r2, uint32_t& r3, uint32_t addr) {
    asm volatile("ldmatrix.sync.aligned.m8n8.x4.shared.b16 {%0,%1,%2,%3}, [%4];"
                 : "=r"(r0), "=r"(r1), "=r"(r2), "=r"(r3) : "r"(addr));
}
__device__ __forceinline__ void ldsm4t(uint32_t& r0, uint32_t& r1, uint32_t& r2, uint32_t& r3, uint32_t addr) {
    asm volatile("ldmatrix.sync.aligned.m8n8.x4.trans.shared.b16 {%0,%1,%2,%3}, [%4];"
                 : "=r"(r0), "=r"(r1), "=r"(r2), "=r"(r3) : "r"(addr));
}
__device__ __forceinline__ void mma16816(float* c, const uint32_t* a, uint32_t b0, uint32_t b1) {
    asm volatile("mma.sync.aligned.m16n8k16.row.col.f32.f16.f16.f32 "
                 "{%0,%1,%2,%3}, {%4,%5,%6,%7}, {%8,%9}, {%0,%1,%2,%3};"
                 : "+f"(c[0]), "+f"(c[1]), "+f"(c[2]), "+f"(c[3])
                 : "r"(a[0]), "r"(a[1]), "r"(a[2]), "r"(a[3]), "r"(b0), "r"(b1));
}
__device__ __forceinline__ void cpa16(uint32_t s, const void* g) {
    asm volatile("cp.async.cg.shared.global [%0], [%1], 16;" :: "r"(s), "l"(g));
}

// ---------------- GEMM1 (fused x-conversion) + layer-1 attention scores -----
// Block tile: 64 rows x 256 cols, K-chunk = 32, 3-stage ring (R14 structure).
#define G1_SS     22016
#define G1_OFF_AH 0
#define G1_OFF_BH 5120
#define G1_SMEM   (3 * G1_SS)

__global__ __launch_bounds__(256, 2) void mma_gemm1(const float* __restrict__ x,
                                                    const float* __restrict__ ah, int M) {
    extern __shared__ __align__(16) char dsm[];
    uint32_t sbase = (uint32_t)__cvta_generic_to_shared(dsm);

    int tid = threadIdx.x;
    int lane = tid & 31, warp = tid >> 5;
    int warpM = (warp >> 2) * 32;
    int warpN = (warp & 3) * 64;
    int blockRow = blockIdx.x * 64;

    int arow = tid >> 2, ak8 = (tid & 3) * 8;
    int agr = blockRow + arow;
    bool aok = (agr < M);
    const float* gA = x + (size_t)agr * NFEAT + ak8;

    uint32_t sBb = sbase + G1_OFF_BH;

    float acc[2][8][4];
#pragma unroll
    for (int a = 0; a < 2; a++)
#pragma unroll
        for (int b = 0; b < 8; b++)
#pragma unroll
            for (int c = 0; c < 4; c++) acc[a][b][c] = 0.f;

    float areg[8];
    auto ldgA = [&](int kc) {
        if (aok) {
            float4 v0 = *(const float4*)(gA + kc * 32);
            float4 v1 = *(const float4*)(gA + kc * 32 + 4);
            areg[0] = v0.x; areg[1] = v0.y; areg[2] = v0.z; areg[3] = v0.w;
            areg[4] = v1.x; areg[5] = v1.y; areg[6] = v1.z; areg[7] = v1.w;
        } else {
#pragma unroll
            for (int j = 0; j < 8; j++) areg[j] = 0.f;
        }
    };
    auto stsA = [&](int st) {
        __half h8[8];
#pragma unroll
        for (int j = 0; j < 8; j++) h8[j] = __float2half_rn(areg[j]);
        *(uint4*)(dsm + st * G1_SS + G1_OFF_AH + (arow * 40 + ak8) * 2) = *(uint4*)h8;
    };
    auto cpB = [&](int kc, int st) {
        int k0 = kc * 32;
#pragma unroll
        for (int it = 0; it < 4; it++) {
            int chunk = it * 256 + tid;
            int brow = chunk >> 5, bc8 = (chunk & 31) * 8;
            cpa16(sBb + st * G1_SS + (uint32_t)(brow * 264 + bc8) * 2,
                  g_Whi + (size_t)(k0 + brow) * HCAT + bc8);
        }
        asm volatile("cp.async.commit_group;");
    };

    ldgA(0);
    cpB(0, 0);
    cpB(1, 1);

    int laneRow = lane & 15;
    int laneSeg = (lane >> 4) * 8;

#pragma unroll
    for (int c = 0; c < 8; c++) {
        int cur = c % 3;
        stsA(cur);
        if (c < 7) ldgA(c + 1);
        if (c + 2 < 8) cpB(c + 2, (c + 2) % 3);
        if (c <= 5)      { asm volatile("cp.async.wait_group 2;"); }
        else if (c == 6) { asm volatile("cp.async.wait_group 1;"); }
        else             { asm volatile("cp.async.wait_group 0;"); }
        __syncthreads();

        uint32_t sb = sbase + cur * G1_SS;
#pragma unroll
        for (int kk = 0; kk < 32; kk += 16) {
            uint32_t ahf[2][4];
#pragma unroll
            for (int mt = 0; mt < 2; mt++) {
                uint32_t ad = sb + G1_OFF_AH +
                    2u * (uint32_t)((warpM + mt * 16 + laneRow) * 40 + kk + laneSeg);
                ldsm4(ahf[mt][0], ahf[mt][1], ahf[mt][2], ahf[mt][3], ad);
            }
#pragma unroll
            for (int nt = 0; nt < 4; nt++) {
                uint32_t bd = sb + G1_OFF_BH +
                    2u * (uint32_t)((kk + laneRow) * 264 + warpN + nt * 16 + laneSeg);
                uint32_t bh0, bh1, bh2, bh3;
                ldsm4t(bh0, bh1, bh2, bh3, bd);
#pragma unroll
                for (int mt = 0; mt < 2; mt++) {
                    mma16816(acc[mt][2 * nt],     ahf[mt], bh0, bh1);
                    mma16816(acc[mt][2 * nt + 1], ahf[mt], bh2, bh3);
                }
            }
        }
        __syncthreads();
    }

#pragma unroll
    for (int mt = 0; mt < 2; mt++) {
#pragma unroll
        for (int n8 = 0; n8 < 8; n8++) {
            int r = blockRow + warpM + mt * 16 + (lane >> 2);
            int cc = warpN + n8 * 8 + (lane & 3) * 2;
            __half2 p0 = __floats2half2_rn(acc[mt][n8][0], acc[mt][n8][1]);
            __half2 p1 = __floats2half2_rn(acc[mt][n8][2], acc[mt][n8][3]);
            *(__half2*)(g_hcat + (size_t)r * HCAT + cc) = p0;
            *(__half2*)(g_hcat + (size_t)(r + 8) * HCAT + cc) = p1;
        }
    }

    int hd = warpN >> 6;
    const float* aH = ah + hd * 128;
    float s_src[2][2] = {{0.f, 0.f}, {0.f, 0.f}};
    float s_dst[2][2] = {{0.f, 0.f}, {0.f, 0.f}};
#pragma unroll
    for (int n8 = 0; n8 < 8; n8++) {
        int cc = n8 * 8 + (lane & 3) * 2;
        float a0 = __ldg(aH + cc),      a1 = __ldg(aH + cc + 1);
        float b0 = __ldg(aH + 64 + cc), b1 = __ldg(aH + 64 + cc + 1);
#pragma unroll
        for (int mt = 0; mt < 2; mt++) {
            s_src[mt][0] += acc[mt][n8][0] * a0 + acc[mt][n8][1] * a1;
            s_dst[mt][0] += acc[mt][n8][0] * b0 + acc[mt][n8][1] * b1;
            s_src[mt][1] += acc[mt][n8][2] * a0 + acc[mt][n8][3] * a1;
            s_dst[mt][1] += acc[mt][n8][2] * b0 + acc[mt][n8][3] * b1;
        }
    }
#pragma unroll
    for (int mt = 0; mt < 2; mt++)
#pragma unroll
        for (int hh = 0; hh < 2; hh++) {
            float s1 = s_src[mt][hh], s2 = s_dst[mt][hh];
            s1 += __shfl_xor_sync(0xffffffffu, s1, 1);
            s1 += __shfl_xor_sync(0xffffffffu, s1, 2);
            s2 += __shfl_xor_sync(0xffffffffu, s2, 1);
            s2 += __shfl_xor_sync(0xffffffffu, s2, 2);
            if ((lane & 3) == 0) {
                int r = blockRow + warpM + mt * 16 + (lane >> 2) + hh * 8;
                g_ss[r * NHEADS + hd] = s1;
                g_sd[r * NHEADS + hd] = s2;
            }
        }
}

// ---------------- CSR construction (5-kernel fork) --------------------------
__global__ void hist_kernel(const int* __restrict__ src, int e) {
    int i = blockIdx.x * blockDim.x + threadIdx.x;
    if (i < e) atomicAdd(&g_deg[src[i]], 1);
}

__global__ __launch_bounds__(1024) void scan1_kernel(int n) {
    __shared__ int s[1024];
    int t = threadIdx.x;
    int idx = blockIdx.x * 1024 + t;
    int v = (idx < n) ? g_deg[idx] : 0;
    s[t] = v;
    __syncthreads();
#pragma unroll
    for (int off = 1; off < 1024; off <<= 1) {
        int x = (t >= off) ? s[t - off] : 0;
        __syncthreads();
        s[t] += x;
        __syncthreads();
    }
    if (idx < n) g_rowptr[idx] = s[t] - v;
    if (t == 1023) g_blocksums[blockIdx.x] = s[1023];
}

__global__ __launch_bounds__(1024) void scan2_kernel(int nb) {
    __shared__ int s[1024];
    int t = threadIdx.x;
    int v = (t < nb) ? g_blocksums[t] : 0;
    s[t] = v;
    __syncthreads();
#pragma unroll
    for (int off = 1; off < 1024; off <<= 1) {
        int x = (t >= off) ? s[t - off] : 0;
        __syncthreads();
        s[t] += x;
        __syncthreads();
    }
    if (t < nb) g_blocksums[t] = s[t] - v;
}

__global__ void scan3_kernel(int n, int e) {
    int i = blockIdx.x * blockDim.x + threadIdx.x;
    if (i < n) {
        int r = g_rowptr[i] + g_blocksums[i >> 10];
        g_rowptr[i] = r;
        g_cursor[i] = r;
    }
    if (i == 0) g_rowptr[n] = e;
}

__global__ void scatter_kernel(const int* __restrict__ src, const int* __restrict__ dst, int e) {
    int i = blockIdx.x * blockDim.x + threadIdx.x;
    if (i < e) {
        int s = src[i];
        int p = atomicAdd(&g_cursor[s], 1);
        g_col[p] = dst[i];
    }
}

// ---------------- layer-1 aggregation (warp per node) -----------------------
// One col LDG per lane + int shuffles for indices; 32-bit row addressing;
// half2 inner accumulation.
__device__ __forceinline__ void accum8(float* acc, uint4 r, float e) {
    float2 f0 = __half22float2(*(__half2*)&r.x);
    float2 f1 = __half22float2(*(__half2*)&r.y);
    float2 f2 = __half22float2(*(__half2*)&r.z);
    float2 f3 = __half22float2(*(__half2*)&r.w);
    acc[0] += e * f0.x; acc[1] += e * f0.y;
    acc[2] += e * f1.x; acc[3] += e * f1.y;
    acc[4] += e * f2.x; acc[5] += e * f2.y;
    acc[6] += e * f3.x; acc[7] += e * f3.y;
}

__device__ __forceinline__ void haccum(__half2* ah, uint4 r, __half2 e2) {
    ah[0] = __hfma2(e2, *(__half2*)&r.x, ah[0]);
    ah[1] = __hfma2(e2, *(__half2*)&r.y, ah[1]);
    ah[2] = __hfma2(e2, *(__half2*)&r.z, ah[2]);
    ah[3] = __hfma2(e2, *(__half2*)&r.w, ah[3]);
}

__global__ void agg1_kernel(int n) {
    int w = (blockIdx.x * blockDim.x + threadIdx.x) >> 5;
    int lane = threadIdx.x & 31;
    if (w >= n) return;
    int start = g_rowptr[w];
    int end = g_rowptr[w + 1];
    int hd = lane >> 3;
    int eidx = lane >> 2;               // edge slot (0..7) this lane serves
    int hidx = lane & 3;                // head for exp duty
    float ss_h = g_ss[w * NHEADS + hidx];
    float acc[8] = {0.f, 0.f, 0.f, 0.f, 0.f, 0.f, 0.f, 0.f};
    float rs32 = 0.f;
    // 32-bit addressing: per-lane base includes lane byte offset
    const char* hbase = (const char*)g_hcat + (lane << 4);
    const __half2 hz = __float2half2_rn(0.f);

    int idx = start;
    for (; idx + 8 <= end; idx += 8) {
        // each lane loads only its own edge's column index (1 LDG, not 8)
        int dval = __ldg(g_col + idx + eidx);
        float ev = __expf(-lrelu(ss_h + __ldg(g_sd + dval * NHEADS + hidx)));
        rs32 += ev;
        // recover all 8 indices via int shuffles (MIO, no LSU pressure)
        unsigned o0 = (unsigned)__shfl_sync(0xffffffffu, dval, 0)  << 9;
        unsigned o1 = (unsigned)__shfl_sync(0xffffffffu, dval, 4)  << 9;
        unsigned o2 = (unsigned)__shfl_sync(0xffffffffu, dval, 8)  << 9;
        unsigned o3 = (unsigned)__shfl_sync(0xffffffffu, dval, 12) << 9;
        unsigned o4 = (unsigned)__shfl_sync(0xffffffffu, dval, 16) << 9;
        unsigned o5 = (unsigned)__shfl_sync(0xffffffffu, dval, 20) << 9;
        unsigned o6 = (unsigned)__shfl_sync(0xffffffffu, dval, 24) << 9;
        unsigned o7 = (unsigned)__shfl_sync(0xffffffffu, dval, 28) << 9;
        uint4 r0 = __ldg((const uint4*)(hbase + o0));
        uint4 r1 = __ldg((const uint4*)(hbase + o1));
        uint4 r2 = __ldg((const uint4*)(hbase + o2));
        uint4 r3 = __ldg((const uint4*)(hbase + o3));
        uint4 r4 = __ldg((const uint4*)(hbase + o4));
        uint4 r5 = __ldg((const uint4*)(hbase + o5));
        uint4 r6 = __ldg((const uint4*)(hbase + o6));
        uint4 r7 = __ldg((const uint4*)(hbase + o7));
        __half2 ah[4] = {hz, hz, hz, hz};
        haccum(ah, r0, __float2half2_rn(__shfl_sync(0xffffffffu, ev, 0 * 4 + hd)));
        haccum(ah, r1, __float2half2_rn(__shfl_sync(0xffffffffu, ev, 1 * 4 + hd)));
        haccum(ah, r2, __float2half2_rn(__shfl_sync(0xffffffffu, ev, 2 * 4 + hd)));
        haccum(ah, r3, __float2half2_rn(__shfl_sync(0xffffffffu, ev, 3 * 4 + hd)));
        haccum(ah, r4, __float2half2_rn(__shfl_sync(0xffffffffu, ev, 4 * 4 + hd)));
        haccum(ah, r5, __float2half2_rn(__shfl_sync(0xffffffffu, ev, 5 * 4 + hd)));
        haccum(ah, r6, __float2half2_rn(__shfl_sync(0xffffffffu, ev, 6 * 4 + hd)));
        haccum(ah, r7, __float2half2_rn(__shfl_sync(0xffffffffu, ev, 7 * 4 + hd)));
        float2 f0 = __half22float2(ah[0]);
        float2 f1 = __half22float2(ah[1]);
        float2 f2 = __half22float2(ah[2]);
        float2 f3 = __half22float2(ah[3]);
        acc[0] += f0.x; acc[1] += f0.y;
        acc[2] += f1.x; acc[3] += f1.y;
        acc[4] += f2.x; acc[5] += f2.y;
        acc[6] += f3.x; acc[7] += f3.y;
    }
    for (; idx < end; idx++) {
        int d = __ldg(g_col + idx);
        float ev = 0.f;
        if (lane < 4) {
            ev = __expf(-lrelu(ss_h + __ldg(g_sd + d * NHEADS + hidx)));
            rs32 += ev;
        }
        uint4 r = __ldg((const uint4*)(hbase + ((unsigned)d << 9)));
        accum8(acc, r, __shfl_sync(0xffffffffu, ev, hd));
    }

    rs32 += __shfl_xor_sync(0xffffffffu, rs32, 4);
    rs32 += __shfl_xor_sync(0xffffffffu, rs32, 8);
    rs32 += __shfl_xor_sync(0xffffffffu, rs32, 16);
    float rs = __shfl_sync(0xffffffffu, rs32, hd);
    float inv = 1.f / rs;

    __half hi8[8];
#pragma unroll
    for (int j = 0; j < 8; j++) {
        hi8[j] = __float2half_rn(eluf(acc[j] * inv));
    }
    *(uint4*)(g_x1hi + (size_t)w * HCAT + lane * 8) = *(uint4*)hi8;
}

// ---------------- GEMM2 (tensor cores) + fused layer-2 scores ---------------
#define G2_OFF_AH 0
#define G2_OFF_BH 67584
#define G2_SMEM   88064

__global__ __launch_bounds__(256) void mma_gemm2(const float* __restrict__ aout) {
    extern __shared__ __align__(16) char dsm[];
    uint32_t sb = (uint32_t)__cvta_generic_to_shared(dsm);
    int tid = threadIdx.x;
    int blockRow = blockIdx.x * 128;

#pragma unroll
    for (int it = 0; it < 16; it++) {
        int chunk = it * 256 + tid;
        int row = chunk >> 5, col8 = (chunk & 31) * 8;
        size_t goff = (size_t)(blockRow + row) * HCAT + col8;
        uint32_t sa = sb + G2_OFF_AH + (uint32_t)(row * 264 + col8) * 2;
        cpa16(sa, g_x1hi + goff);
    }
#pragma unroll
    for (int it = 0; it < 4; it++) {
        int chunk = it * 256 + tid;
        int row = chunk >> 2, col8 = (chunk & 3) * 8;
        uint32_t sB = sb + G2_OFF_BH + (uint32_t)(row * 40 + col8) * 2;
        cpa16(sB, g_W2hi + row * NCLASS + col8);
    }
    asm volatile("cp.async.commit_group;");
    asm volatile("cp.async.wait_group 0;");
    __syncthreads();

    int warp = tid >> 5, lane = tid & 31;
    int laneRow = lane & 15, laneSeg = (lane >> 4) * 8;
    float acc[4][4];
#pragma unroll
    for (int a = 0; a < 4; a++)
#pragma unroll
        for (int c = 0; c < 4; c++) acc[a][c] = 0.f;

#pragma unroll
    for (int kk = 0; kk < 256; kk += 16) {
        uint32_t ad = sb + G2_OFF_AH + 2u * (uint32_t)((warp * 16 + laneRow) * 264 + kk + laneSeg);
        uint32_t ahf[4];
        ldsm4(ahf[0], ahf[1], ahf[2], ahf[3], ad);
#pragma unroll
        for (int nt = 0; nt < 2; nt++) {
            uint32_t bd = sb + G2_OFF_BH + 2u * (uint32_t)((kk + laneRow) * 40 + nt * 16 + laneSeg);
            uint32_t bh0, bh1, bh2, bh3;
            ldsm4t(bh0, bh1, bh2, bh3, bd);
            mma16816(acc[2 * nt],     ahf, bh0, bh1);
            mma16816(acc[2 * nt + 1], ahf, bh2, bh3);
        }
    }

    int r0 = blockRow + warp * 16 + (lane >> 2);
    float s1[2] = {0.f, 0.f}, s2[2] = {0.f, 0.f};
#pragma unroll
    for (int n8 = 0; n8 < 4; n8++) {
        int cc = n8 * 8 + (lane & 3) * 2;
        float a0 = __ldg(aout + cc),      a1 = __ldg(aout + cc + 1);
        float b0 = __ldg(aout + 32 + cc), b1 = __ldg(aout + 32 + cc + 1);
        *(__half2*)(g_h2h + (size_t)r0 * NCLASS + cc) = __floats2half2_rn(acc[n8][0], acc[n8][1]);
        *(__half2*)(g_h2h + (size_t)(r0 + 8) * NCLASS + cc) = __floats2half2_rn(acc[n8][2], acc[n8][3]);
        s1[0] += acc[n8][0] * a0 + acc[n8][1] * a1;
        s2[0] += acc[n8][0] * b0 + acc[n8][1] * b1;
        s1[1] += acc[n8][2] * a0 + acc[n8][3] * a1;
        s2[1] += acc[n8][2] * b0 + acc[n8][3] * b1;
    }
#pragma unroll
    for (int hh = 0; hh < 2; hh++) {
        float p1 = s1[hh], p2 = s2[hh];
        p1 += __shfl_xor_sync(0xffffffffu, p1, 1);
        p1 += __shfl_xor_sync(0xffffffffu, p1, 2);
        p2 += __shfl_xor_sync(0xffffffffu, p2, 1);
        p2 += __shfl_xor_sync(0xffffffffu, p2, 2);
        if ((lane & 3) == 0) {
            g_ss2[r0 + hh * 8] = p1;
            g_sd2[r0 + hh * 8] = p2;
        }
    }
}

// ---------------- layer-2 aggregation + elu + log_softmax ------------------
__global__ void agg2_kernel(float* __restrict__ out, int n) {
    int w = (blockIdx.x * blockDim.x + threadIdx.x) >> 5;
    int lane = threadIdx.x & 31;
    if (w >= n) return;
    int start = g_rowptr[w];
    int end = g_rowptr[w + 1];
    float ssn = g_ss2[w];
    int myoff = lane >> 4;
    int cpos = (lane & 15) * 2;
    float ax = 0.f, ay = 0.f, rs = 0.f;

    int idx = start;
    for (; idx + 16 <= end; idx += 16) {
        int d[8];
#pragma unroll
        for (int p = 0; p < 8; p++) d[p] = __ldg(g_col + idx + p * 2 + myoff);
        float ev[8];
#pragma unroll
        for (int p = 0; p < 8; p++) ev[p] = __expf(-lrelu(ssn + __ldg(g_sd2 + d[p])));
        float2 hv[8];
#pragma unroll
        for (int p = 0; p < 8; p++)
            hv[p] = __half22float2(__ldg((const __half2*)(g_h2h + (size_t)d[p] * NCLASS + cpos)));
#pragma unroll
        for (int p = 0; p < 8; p++) {
            ax += ev[p] * hv[p].x;
            ay += ev[p] * hv[p].y;
            rs += ev[p];
        }
    }
    for (; idx + 2 <= end; idx += 2) {
        int d = __ldg(g_col + idx + myoff);
        float ev = __expf(-lrelu(ssn + __ldg(g_sd2 + d)));
        float2 hv = __half22float2(__ldg((const __half2*)(g_h2h + (size_t)d * NCLASS + cpos)));
        ax += ev * hv.x; ay += ev * hv.y; rs += ev;
    }
    if (idx < end) {
        int d = __ldg(g_col + idx);
        if (lane < 16) {
            float ev = __expf(-lrelu(ssn + __ldg(g_sd2 + d)));
            float2 hv = __half22float2(__ldg((const __half2*)(g_h2h + (size_t)d * NCLASS + cpos)));
            ax += ev * hv.x; ay += ev * hv.y; rs += ev;
        }
    }

    ax += __shfl_xor_sync(0xffffffffu, ax, 16);
    ay += __shfl_xor_sync(0xffffffffu, ay, 16);
    rs += __shfl_xor_sync(0xffffffffu, rs, 16);

    float inv = 1.f / rs;
    float vx = eluf(ax * inv);
    float vy = eluf(ay * inv);
    float m = fmaxf(vx, vy);
#pragma unroll
    for (int off = 8; off; off >>= 1) m = fmaxf(m, __shfl_xor_sync(0xffffffffu, m, off));
    float sum = __expf(vx - m) + __expf(vy - m);
#pragma unroll
    for (int off = 8; off; off >>= 1) sum += __shfl_xor_sync(0xffffffffu, sum, off);
    float ls = __logf(sum);
    if (lane < 16) {
        *(float2*)(out + (size_t)w * NCLASS + cpos) = make_float2(vx - m - ls, vy - m - ls);
    }
}

// ---------------- launch ----------------------------------------------------
extern "C" void kernel_launch(void* const* d_in, const int* in_sizes, int n_in,
                              void* d_out, int out_size) {
    const float* x = (const float*)d_in[0];
    const int* edge = (const int*)d_in[1];
    const float* W_heads = (const float*)d_in[2];
    const float* a_heads = (const float*)d_in[3];
    const float* W_out = (const float*)d_in[4];
    const float* a_out = (const float*)d_in[5];
    float* out = (float*)d_out;

    int n = in_sizes[0] / NFEAT;       // 100000
    int e = in_sizes[1] / 2;           // 1600000
    const int* src = edge;
    const int* dst = edge + e;

    static cudaStream_t s_side = nullptr;
    static cudaEvent_t ev_fork = nullptr, ev_join = nullptr;
    if (s_side == nullptr) {
        cudaFuncSetAttribute(mma_gemm1, cudaFuncAttributeMaxDynamicSharedMemorySize, G1_SMEM);
        cudaFuncSetAttribute(mma_gemm2, cudaFuncAttributeMaxDynamicSharedMemorySize, G2_SMEM);
        cudaStreamCreateWithFlags(&s_side, cudaStreamNonBlocking);
        cudaEventCreateWithFlags(&ev_fork, cudaEventDisableTiming);
        cudaEventCreateWithFlags(&ev_join, cudaEventDisableTiming);
    }

    // prep (W conversion + deg zero) must precede fork (hist needs g_deg=0)
    int prep_elems = NHEADS * NFEAT * NHID;
    int prep_grid = ((prep_elems > n ? prep_elems : n) + 255) / 256;
    prep_kernel<<<prep_grid, 256>>>(W_heads, W_out, n);   // launch 1

    // fork: CSR construction on side stream, overlapped with GEMM1
    cudaEventRecord(ev_fork, 0);
    cudaStreamWaitEvent(s_side, ev_fork, 0);
    hist_kernel<<<(e + 255) / 256, 256, 0, s_side>>>(src, e);          // launch 2
    int nb = (n + 1023) / 1024;
    scan1_kernel<<<nb, 1024, 0, s_side>>>(n);                          // launch 3

    // main stream: fused-conversion GEMM1
    mma_gemm1<<<(n + 63) / 64, 256, G1_SMEM>>>(x, a_heads, n);         // launch 4

    scan2_kernel<<<1, 1024, 0, s_side>>>(nb);                          // launch 5
    scan3_kernel<<<(n + 255) / 256, 256, 0, s_side>>>(n, e);           // launch 6
    scatter_kernel<<<(e + 255) / 256, 256, 0, s_side>>>(src, dst, e);  // launch 7
    cudaEventRecord(ev_join, s_side);

    // join: aggregation needs CSR
    cudaStreamWaitEvent(0, ev_join, 0);

    int nwarp_blocks = (n + 7) / 8;
    agg1_kernel<<<nwarp_blocks, 256>>>(n);                             // launch 8
    mma_gemm2<<<(n + 127) / 128, 256, G2_SMEM>>>(a_out);               // launch 9
    agg2_kernel<<<nwarp_blocks, 256>>>(out, n);                        // launch 10
}